// round 1
// baseline (speedup 1.0000x reference)
#include <cuda_runtime.h>
#include <cuda_bf16.h>

#define N_RES 1024
#define C_M   256
#define C_Z   128
#define NUM_BINS 15
#define LN_EPS 1e-5f

// ---------------------------------------------------------------------------
// Kernel A: LayerNorm of m [N_RES, C_M]. One warp per row, 8 floats per lane.
// ---------------------------------------------------------------------------
__global__ void __launch_bounds__(256) m_ln_kernel(
    const float* __restrict__ m,
    const float* __restrict__ w,
    const float* __restrict__ b,
    float* __restrict__ out)
{
    int warp = (blockIdx.x * blockDim.x + threadIdx.x) >> 5;
    int lane = threadIdx.x & 31;
    if (warp >= N_RES) return;

    const float4* row = reinterpret_cast<const float4*>(m + (size_t)warp * C_M);
    float4 v0 = row[lane];
    float4 v1 = row[lane + 32];

    float s  = v0.x + v0.y + v0.z + v0.w + v1.x + v1.y + v1.z + v1.w;
    float s2 = v0.x*v0.x + v0.y*v0.y + v0.z*v0.z + v0.w*v0.w
             + v1.x*v1.x + v1.y*v1.y + v1.z*v1.z + v1.w*v1.w;
#pragma unroll
    for (int o = 16; o; o >>= 1) {
        s  += __shfl_xor_sync(0xffffffffu, s,  o);
        s2 += __shfl_xor_sync(0xffffffffu, s2, o);
    }
    float mu  = s * (1.0f / C_M);
    float var = s2 * (1.0f / C_M) - mu * mu;
    float inv = rsqrtf(var + LN_EPS);

    float4* orow = reinterpret_cast<float4*>(out + (size_t)warp * C_M);
    int c0 = lane * 4;
    float4 r0, r1;
    r0.x = (v0.x - mu) * inv * w[c0 + 0]   + b[c0 + 0];
    r0.y = (v0.y - mu) * inv * w[c0 + 1]   + b[c0 + 1];
    r0.z = (v0.z - mu) * inv * w[c0 + 2]   + b[c0 + 2];
    r0.w = (v0.w - mu) * inv * w[c0 + 3]   + b[c0 + 3];
    r1.x = (v1.x - mu) * inv * w[c0 + 128] + b[c0 + 128];
    r1.y = (v1.y - mu) * inv * w[c0 + 129] + b[c0 + 129];
    r1.z = (v1.z - mu) * inv * w[c0 + 130] + b[c0 + 130];
    r1.w = (v1.w - mu) * inv * w[c0 + 131] + b[c0 + 131];
    orow[lane]      = r0;
    orow[lane + 32] = r1;
}

// ---------------------------------------------------------------------------
// Kernel B: z LayerNorm + distogram add. One warp per (i,j) row (128 floats,
// 1 float4/lane). 8 warps per block. dtab[k][c] = lin_w[c,k] + lin_b[c],
// row 15 = lin_b alone (one-hot all zero case).
// ---------------------------------------------------------------------------
__global__ void __launch_bounds__(256) z_fused_kernel(
    const float* __restrict__ z,
    const float* __restrict__ x,
    const float* __restrict__ lnw,
    const float* __restrict__ lnb,
    const float* __restrict__ lin_w,
    const float* __restrict__ lin_b,
    float* __restrict__ out)
{
    __shared__ float dtab[16][C_Z];
    __shared__ float sw[C_Z];
    __shared__ float sb[C_Z];

    int tid = threadIdx.x;
#pragma unroll
    for (int idx = tid; idx < 16 * C_Z; idx += 256) {
        int k = idx >> 7;
        int c = idx & (C_Z - 1);
        float v = lin_b[c];
        if (k < NUM_BINS) v += lin_w[c * NUM_BINS + k];
        dtab[k][c] = v;
    }
    if (tid < C_Z) { sw[tid] = lnw[tid]; sb[tid] = lnb[tid]; }
    __syncthreads();

    int warp = tid >> 5;
    int lane = tid & 31;
    long long row = (long long)blockIdx.x * 8 + warp;   // 0 .. N*N-1
    int i = (int)(row >> 10);
    int j = (int)(row & (N_RES - 1));

    // squared distance (uniform across warp; LDG broadcast)
    float dx = x[3 * i + 0] - x[3 * j + 0];
    float dy = x[3 * i + 1] - x[3 * j + 1];
    float dz = x[3 * i + 2] - x[3 * j + 2];
    float d2 = dx * dx + dy * dy + dz * dz;

    int k = NUM_BINS;   // default: no bin matched -> lin_b only
#pragma unroll
    for (int bb = 0; bb < NUM_BINS; ++bb) {
        float lo = (3.25f + 1.25f * bb);
        lo = lo * lo;
        float hi;
        if (bb < NUM_BINS - 1) {
            hi = (3.25f + 1.25f * (bb + 1));
            hi = hi * hi;
        } else {
            hi = 1e8f;
        }
        if (d2 > lo && d2 < hi) k = bb;
    }

    const float4* zr = reinterpret_cast<const float4*>(z + row * C_Z);
    float4 v = zr[lane];

    float s  = v.x + v.y + v.z + v.w;
    float s2 = v.x*v.x + v.y*v.y + v.z*v.z + v.w*v.w;
#pragma unroll
    for (int o = 16; o; o >>= 1) {
        s  += __shfl_xor_sync(0xffffffffu, s,  o);
        s2 += __shfl_xor_sync(0xffffffffu, s2, o);
    }
    float mu  = s * (1.0f / C_Z);
    float var = s2 * (1.0f / C_Z) - mu * mu;
    float inv = rsqrtf(var + LN_EPS);

    int c0 = lane * 4;
    float4 o;
    o.x = (v.x - mu) * inv * sw[c0 + 0] + sb[c0 + 0] + dtab[k][c0 + 0];
    o.y = (v.y - mu) * inv * sw[c0 + 1] + sb[c0 + 1] + dtab[k][c0 + 1];
    o.z = (v.z - mu) * inv * sw[c0 + 2] + sb[c0 + 2] + dtab[k][c0 + 2];
    o.w = (v.w - mu) * inv * sw[c0 + 3] + sb[c0 + 3] + dtab[k][c0 + 3];

    reinterpret_cast<float4*>(out + row * C_Z)[lane] = o;
}

extern "C" void kernel_launch(void* const* d_in, const int* in_sizes, int n_in,
                              void* d_out, int out_size)
{
    const float* m     = (const float*)d_in[0];
    const float* z     = (const float*)d_in[1];
    const float* x     = (const float*)d_in[2];
    const float* ln_m_w = (const float*)d_in[3];
    const float* ln_m_b = (const float*)d_in[4];
    const float* ln_z_w = (const float*)d_in[5];
    const float* ln_z_b = (const float*)d_in[6];
    const float* lin_w = (const float*)d_in[7];
    const float* lin_b = (const float*)d_in[8];

    float* out_m = (float*)d_out;                       // [N_RES, C_M]
    float* out_z = out_m + (size_t)N_RES * C_M;         // [N_RES, N_RES, C_Z]

    // m layernorm: 1024 rows, 1 warp each, 8 warps/block -> 128 blocks
    m_ln_kernel<<<N_RES / 8, 256>>>(m, ln_m_w, ln_m_b, out_m);

    // z fused: 1024*1024 rows, 1 warp each, 8 warps/block -> 131072 blocks
    z_fused_kernel<<<(N_RES * N_RES) / 8, 256>>>(
        z, x, ln_z_w, ln_z_b, lin_w, lin_b, out_z);
}

// round 3
// speedup vs baseline: 1.6678x; 1.6678x over previous
#include <cuda_runtime.h>
#include <cuda_bf16.h>

#define N_RES 1024
#define C_M   256
#define C_Z   128
#define NUM_BINS 15
#define LN_EPS 1e-5f
#define ROWS_PER_WARP 4

// Fused distogram+bias table: g_dtab[k][c] = ln_z_b[c] + lin_b[c] + (k<15 ? lin_w[c,k] : 0)
__device__ float g_dtab[16 * C_Z];

// ---------------------------------------------------------------------------
// Table build: 2048 entries.
// ---------------------------------------------------------------------------
__global__ void dtab_kernel(const float* __restrict__ lnb,
                            const float* __restrict__ lin_w,
                            const float* __restrict__ lin_b)
{
    int idx = blockIdx.x * blockDim.x + threadIdx.x;   // 0..2047
    int k = idx >> 7;
    int c = idx & (C_Z - 1);
    float v = lnb[c] + lin_b[c];
    if (k < NUM_BINS) v += lin_w[c * NUM_BINS + k];
    g_dtab[idx] = v;
}

// ---------------------------------------------------------------------------
// LayerNorm of m [N_RES, C_M]. One warp per row.
// ---------------------------------------------------------------------------
__global__ void __launch_bounds__(256) m_ln_kernel(
    const float* __restrict__ m,
    const float* __restrict__ w,
    const float* __restrict__ b,
    float* __restrict__ out)
{
    int warp = (blockIdx.x * blockDim.x + threadIdx.x) >> 5;
    int lane = threadIdx.x & 31;
    if (warp >= N_RES) return;

    const float4* row = reinterpret_cast<const float4*>(m + (size_t)warp * C_M);
    float4 v0 = row[lane];
    float4 v1 = row[lane + 32];

    float s  = v0.x + v0.y + v0.z + v0.w + v1.x + v1.y + v1.z + v1.w;
    float s2 = v0.x*v0.x + v0.y*v0.y + v0.z*v0.z + v0.w*v0.w
             + v1.x*v1.x + v1.y*v1.y + v1.z*v1.z + v1.w*v1.w;
#pragma unroll
    for (int o = 16; o; o >>= 1) {
        s  += __shfl_xor_sync(0xffffffffu, s,  o);
        s2 += __shfl_xor_sync(0xffffffffu, s2, o);
    }
    float mu  = s * (1.0f / C_M);
    float var = s2 * (1.0f / C_M) - mu * mu;
    float inv = rsqrtf(var + LN_EPS);

    float4* orow = reinterpret_cast<float4*>(out + (size_t)warp * C_M);
    int c0 = lane * 4;
    float4 r0, r1;
    r0.x = (v0.x - mu) * inv * w[c0 + 0]   + b[c0 + 0];
    r0.y = (v0.y - mu) * inv * w[c0 + 1]   + b[c0 + 1];
    r0.z = (v0.z - mu) * inv * w[c0 + 2]   + b[c0 + 2];
    r0.w = (v0.w - mu) * inv * w[c0 + 3]   + b[c0 + 3];
    r1.x = (v1.x - mu) * inv * w[c0 + 128] + b[c0 + 128];
    r1.y = (v1.y - mu) * inv * w[c0 + 129] + b[c0 + 129];
    r1.z = (v1.z - mu) * inv * w[c0 + 130] + b[c0 + 130];
    r1.w = (v1.w - mu) * inv * w[c0 + 131] + b[c0 + 131];
    orow[lane]      = r0;
    orow[lane + 32] = r1;
}

// ---------------------------------------------------------------------------
// z LayerNorm + distogram add. One warp per 4 consecutive (i,j) rows.
// All per-channel constants folded into g_dtab; ln weight in registers.
// Reductions for all 4 rows interleaved -> 8 independent SHFL chains (ILP).
// ---------------------------------------------------------------------------
__global__ void __launch_bounds__(256) z_fused_kernel(
    const float* __restrict__ z,
    const float* __restrict__ x,
    const float* __restrict__ lnw,
    float* __restrict__ out)
{
    int lane = threadIdx.x & 31;
    long long row0 = (long long)((blockIdx.x * blockDim.x + threadIdx.x) >> 5)
                   * ROWS_PER_WARP;
    int i  = (int)(row0 >> 10);
    int j0 = (int)(row0 & (N_RES - 1));   // row0 % 4 == 0 -> same i for all 4 rows

    // Front-batched streaming loads (MLP=4)
    const float4* zr = reinterpret_cast<const float4*>(z + row0 * C_Z) + lane;
    float4 v[ROWS_PER_WARP];
#pragma unroll
    for (int r = 0; r < ROWS_PER_WARP; ++r)
        v[r] = __ldcs(zr + r * 32);

    // Bin index per row (warp-uniform, arithmetic instead of 15-way loop)
    float xi0 = x[3 * i + 0], xi1 = x[3 * i + 1], xi2 = x[3 * i + 2];
    int kb[ROWS_PER_WARP];
#pragma unroll
    for (int r = 0; r < ROWS_PER_WARP; ++r) {
        int j = j0 + r;
        float dx = xi0 - x[3 * j + 0];
        float dy = xi1 - x[3 * j + 1];
        float dz = xi2 - x[3 * j + 2];
        float d2 = dx * dx + dy * dy + dz * dz;
        int kk = __float2int_rd((__fsqrt_rn(d2) - 3.25f) * 0.8f);
        kk = min(max(kk, 0), NUM_BINS - 1);
        kb[r] = (d2 <= 10.5625f) ? NUM_BINS : kk;   // 10.5625 = 3.25^2
    }

    // Interleaved reductions: 8 independent shuffle chains
    float s[ROWS_PER_WARP], s2[ROWS_PER_WARP];
#pragma unroll
    for (int r = 0; r < ROWS_PER_WARP; ++r) {
        float4 vv = v[r];
        s[r]  = vv.x + vv.y + vv.z + vv.w;
        s2[r] = vv.x*vv.x + vv.y*vv.y + vv.z*vv.z + vv.w*vv.w;
    }
#pragma unroll
    for (int o = 16; o; o >>= 1) {
#pragma unroll
        for (int r = 0; r < ROWS_PER_WARP; ++r) {
            s[r]  += __shfl_xor_sync(0xffffffffu, s[r],  o);
            s2[r] += __shfl_xor_sync(0xffffffffu, s2[r], o);
        }
    }

    int c0 = lane * 4;
    float4 sw4 = *reinterpret_cast<const float4*>(lnw + c0);
    float4* orow = reinterpret_cast<float4*>(out + row0 * C_Z) + lane;

#pragma unroll
    for (int r = 0; r < ROWS_PER_WARP; ++r) {
        float mu  = s[r] * (1.0f / C_Z);
        float var = s2[r] * (1.0f / C_Z) - mu * mu;
        float inv = rsqrtf(var + LN_EPS);

        float4 d4 = *reinterpret_cast<const float4*>(g_dtab + kb[r] * C_Z + c0);
        float4 vv = v[r];
        float4 o;
        o.x = (vv.x - mu) * (inv * sw4.x) + d4.x;
        o.y = (vv.y - mu) * (inv * sw4.y) + d4.y;
        o.z = (vv.z - mu) * (inv * sw4.z) + d4.z;
        o.w = (vv.w - mu) * (inv * sw4.w) + d4.w;
        __stcs(orow + r * 32, o);
    }
}

extern "C" void kernel_launch(void* const* d_in, const int* in_sizes, int n_in,
                              void* d_out, int out_size)
{
    const float* m      = (const float*)d_in[0];
    const float* z      = (const float*)d_in[1];
    const float* x      = (const float*)d_in[2];
    const float* ln_m_w = (const float*)d_in[3];
    const float* ln_m_b = (const float*)d_in[4];
    const float* ln_z_w = (const float*)d_in[5];
    const float* ln_z_b = (const float*)d_in[6];
    const float* lin_w  = (const float*)d_in[7];
    const float* lin_b  = (const float*)d_in[8];

    float* out_m = (float*)d_out;                   // [N_RES, C_M]
    float* out_z = out_m + (size_t)N_RES * C_M;     // [N_RES, N_RES, C_Z]

    dtab_kernel<<<8, 256>>>(ln_z_b, lin_w, lin_b);

    m_ln_kernel<<<N_RES / 8, 256>>>(m, ln_m_w, ln_m_b, out_m);

    // 1M rows / (8 warps * 4 rows) = 32768 blocks
    z_fused_kernel<<<(N_RES * N_RES) / (8 * ROWS_PER_WARP), 256>>>(
        z, x, ln_z_w, out_z);
}